// round 14
// baseline (speedup 1.0000x reference)
#include <cuda_runtime.h>
#include <cstdint>

#define NN 4096
#define NE 8192
#define NLG 32768
#define HA 16384
#define HL 65536
#define ELLW 32

// ---------------- static scratch ----------------
__device__ int g_hkA[HA], g_hwA[HA];
__device__ int g_hkL[HL], g_hwL[HL];
__device__ int g_hkU[HL], g_hwU[HL];
__device__ int g_cntA[NN], g_cntL[NE], g_cntU[NE];
__device__ int g_ellA[NN*ELLW], g_ellL[NE*ELLW], g_ellU[NE*ELLW];
__device__ float g_valL[NE*ELLW], g_valU[NE*ELLW];

__device__ float g_ncat0[NN*192];
__device__ float g_ncat1[NN*384];
__device__ float g_hn[NN*128];
__device__ float g_ecat0[NE*160];
__device__ float g_ecat1[NE*640];
__device__ float g_he[NE*128];
__device__ float g_he2[NE*128];
__device__ float g_ws0[160*128];
__device__ float g_ws1[640*128];

__device__ __forceinline__ unsigned hmix(unsigned key) {
    return (key * 2654435761u) >> 7;
}

// packed f32x2 helpers
__device__ __forceinline__ unsigned long long pack_dup(float v) {
    unsigned long long r;
    unsigned u = __float_as_uint(v);
    asm("mov.b64 %0, {%1, %1};" : "=l"(r) : "r"(u));
    return r;
}
__device__ __forceinline__ void fma2(unsigned long long& acc, unsigned long long a,
                                     unsigned long long b) {
    asm("fma.rn.f32x2 %0, %1, %2, %0;" : "+l"(acc) : "l"(a), "l"(b));
}
__device__ __forceinline__ float lo32(unsigned long long v) {
    return __uint_as_float((unsigned)(v & 0xFFFFFFFFull));
}
__device__ __forceinline__ float hi32(unsigned long long v) {
    return __uint_as_float((unsigned)(v >> 32));
}

// ---------------- init: tables, stacked weights, input copies ----------------
__global__ void init_k(const float* __restrict__ eWl0, const float* __restrict__ eWu0,
                       const float* __restrict__ eWl1, const float* __restrict__ eWu1,
                       const float* __restrict__ x, const float* __restrict__ ex) {
    cudaGridDependencySynchronize();
    int i = blockIdx.x * blockDim.x + threadIdx.x;
    int stride = gridDim.x * blockDim.x;
    for (int j = i; j < HA; j += stride) { g_hkA[j] = -1; g_hwA[j] = -1; }
    for (int j = i; j < HL; j += stride) { g_hkL[j] = -1; g_hwL[j] = -1;
                                           g_hkU[j] = -1; g_hwU[j] = -1; }
    for (int j = i; j < NN; j += stride) g_cntA[j] = 0;
    for (int j = i; j < NE; j += stride) { g_cntL[j] = 0; g_cntU[j] = 0; }
    for (int j = i; j < 32*128; j += stride)  g_ws0[j] = eWl0[j] + eWu0[j];
    for (int j = i; j < 64*128; j += stride) {
        g_ws0[32*128 + j] = eWl0[32*128 + j];
        g_ws0[96*128 + j] = eWu0[32*128 + j];
    }
    for (int j = i; j < 128*128; j += stride) g_ws1[j] = eWl1[j] + eWu1[j];
    for (int j = i; j < 256*128; j += stride) {
        g_ws1[128*128 + j] = eWl1[128*128 + j];
        g_ws1[384*128 + j] = eWu1[128*128 + j];
    }
    for (int j = i; j < NN*16; j += stride) {
        int r = j >> 4, c = j & 15;
        *(float4*)(g_ncat0 + (size_t)r*192 + c*4) = *(const float4*)(x + (size_t)r*64 + c*4);
    }
    for (int j = i; j < NE*8; j += stride) {
        int r = j >> 3, c = j & 7;
        *(float4*)(g_ecat0 + (size_t)r*160 + c*4) = *(const float4*)(ex + (size_t)r*32 + c*4);
    }
}

// ---------------- dedup p1 ----------------
__global__ void p1_all(const int* __restrict__ nei, const int* __restrict__ eil,
                       const int* __restrict__ eiu) {
    cudaGridDependencySynchronize();
    int i = blockIdx.x * blockDim.x + threadIdx.x;
    int *hkey, *hwin; unsigned key, mask; int idx;
    if (i < NE) {
        idx = i; key = (unsigned)nei[i] * NN + (unsigned)nei[NE + i];
        hkey = g_hkA; hwin = g_hwA; mask = HA - 1;
    } else if (i < NE + NLG) {
        idx = i - NE; key = (unsigned)eil[idx] * NE + (unsigned)eil[NLG + idx];
        hkey = g_hkL; hwin = g_hwL; mask = HL - 1;
    } else if (i < NE + 2*NLG) {
        idx = i - NE - NLG; key = (unsigned)eiu[idx] * NE + (unsigned)eiu[NLG + idx];
        hkey = g_hkU; hwin = g_hwU; mask = HL - 1;
    } else return;
    unsigned h = hmix(key) & mask;
    while (true) {
        int prev = atomicCAS(&hkey[h], -1, (int)key);
        if (prev == -1 || prev == (int)key) { atomicMax(&hwin[h], idx); return; }
        h = (h + 1) & mask;
    }
}

// ---------------- dedup p2 + ELL fill ----------------
__global__ void p2_fill(const int* __restrict__ nei, const int* __restrict__ eil,
                        const int* __restrict__ eiu, const float* __restrict__ eal,
                        const float* __restrict__ eau) {
    cudaGridDependencySynchronize();
    int i = blockIdx.x * blockDim.x + threadIdx.x;
    const int *hkey, *hwin; unsigned key, mask; int idx, row, col; float w;
    int *cnt, *ell; float* vals;
    if (i < NE) {
        idx = i; row = nei[i]; col = nei[NE + i]; w = 1.f;
        key = (unsigned)row * NN + (unsigned)col;
        hkey = g_hkA; hwin = g_hwA; mask = HA - 1;
        cnt = g_cntA; ell = g_ellA; vals = nullptr;
    } else if (i < NE + NLG) {
        idx = i - NE; row = eil[idx]; col = eil[NLG + idx]; w = eal[idx];
        key = (unsigned)row * NE + (unsigned)col;
        hkey = g_hkL; hwin = g_hwL; mask = HL - 1;
        cnt = g_cntL; ell = g_ellL; vals = g_valL;
    } else if (i < NE + 2*NLG) {
        idx = i - NE - NLG; row = eiu[idx]; col = eiu[NLG + idx]; w = eau[idx];
        key = (unsigned)row * NE + (unsigned)col;
        hkey = g_hkU; hwin = g_hwU; mask = HL - 1;
        cnt = g_cntU; ell = g_ellU; vals = g_valU;
    } else return;
    unsigned h = hmix(key) & mask;
    while (hkey[h] != (int)key) h = (h + 1) & mask;
    if (hwin[h] != idx) return;
    int p = atomicAdd(&cnt[row], 1);
    if (p >= ELLW) return;
    int o = row * ELLW + p;
    ell[o] = col;
    if (vals) vals[o] = w;
}

// ---------------- ELL SpMM helpers (2-way MLP unroll) ----------------
// 4 floats per thread
__device__ __forceinline__ void spmmE4(const int* __restrict__ cnt, const int* __restrict__ ell,
                                       const float* __restrict__ vals,
                                       const float* __restrict__ X, int ld,
                                       float* __restrict__ Y, int nc4, int idx) {
    int r = idx / nc4, c = idx - r * nc4;
    int len = cnt[r];
    int base = r * ELLW;
    float4 acc = make_float4(0.f,0.f,0.f,0.f);
    int j = 0;
    for (; j + 2 <= len; j += 2) {
        int c0 = ell[base + j], c1 = ell[base + j + 1];
        float w0 = vals ? vals[base + j] : 1.0f;
        float w1 = vals ? vals[base + j + 1] : 1.0f;
        float4 x0 = *(const float4*)(X + (size_t)c0 * ld + c * 4);
        float4 x1 = *(const float4*)(X + (size_t)c1 * ld + c * 4);
        acc.x += w0*x0.x + w1*x1.x; acc.y += w0*x0.y + w1*x1.y;
        acc.z += w0*x0.z + w1*x1.z; acc.w += w0*x0.w + w1*x1.w;
    }
    if (j < len) {
        int c0 = ell[base + j];
        float w0 = vals ? vals[base + j] : 1.0f;
        float4 x0 = *(const float4*)(X + (size_t)c0 * ld + c * 4);
        acc.x += w0*x0.x; acc.y += w0*x0.y; acc.z += w0*x0.z; acc.w += w0*x0.w;
    }
    *(float4*)(Y + (size_t)r * ld + c * 4) = acc;
}

// 8 floats per thread
__device__ __forceinline__ void spmmE8(const int* __restrict__ cnt, const int* __restrict__ ell,
                                       const float* __restrict__ vals,
                                       const float* __restrict__ X, int ld,
                                       float* __restrict__ Y, int nc8, int idx) {
    int r = idx / nc8, c = idx - r * nc8;
    int len = cnt[r];
    int base = r * ELLW;
    float4 a0 = make_float4(0.f,0.f,0.f,0.f), a1 = a0;
    int j = 0;
    for (; j + 2 <= len; j += 2) {
        int c0 = ell[base + j], c1 = ell[base + j + 1];
        float w0 = vals ? vals[base + j] : 1.0f;
        float w1 = vals ? vals[base + j + 1] : 1.0f;
        const float4* p0 = (const float4*)(X + (size_t)c0 * ld + c * 8);
        const float4* p1 = (const float4*)(X + (size_t)c1 * ld + c * 8);
        float4 x00 = p0[0], x01 = p0[1], x10 = p1[0], x11 = p1[1];
        a0.x += w0*x00.x + w1*x10.x; a0.y += w0*x00.y + w1*x10.y;
        a0.z += w0*x00.z + w1*x10.z; a0.w += w0*x00.w + w1*x10.w;
        a1.x += w0*x01.x + w1*x11.x; a1.y += w0*x01.y + w1*x11.y;
        a1.z += w0*x01.z + w1*x11.z; a1.w += w0*x01.w + w1*x11.w;
    }
    if (j < len) {
        int c0 = ell[base + j];
        float w0 = vals ? vals[base + j] : 1.0f;
        const float4* p0 = (const float4*)(X + (size_t)c0 * ld + c * 8);
        float4 x00 = p0[0], x01 = p0[1];
        a0.x += w0*x00.x; a0.y += w0*x00.y; a0.z += w0*x00.z; a0.w += w0*x00.w;
        a1.x += w0*x01.x; a1.y += w0*x01.y; a1.z += w0*x01.z; a1.w += w0*x01.w;
    }
    float4* yp = (float4*)(Y + (size_t)r * ld + c * 8);
    yp[0] = a0; yp[1] = a1;
}

// hop0: float4 granularity (more threads for latency hiding)
__global__ void hop0a() {
    cudaGridDependencySynchronize();
    int i = blockIdx.x * blockDim.x + threadIdx.x;
    const int S0 = NN*16, S1 = S0 + NE*8, S2 = S1 + NE*8;
    if (i < S0)       spmmE4(g_cntA, g_ellA, nullptr, g_ncat0, 192, g_ncat0 + 64, 16, i);
    else if (i < S1)  spmmE4(g_cntL, g_ellL, g_valL, g_ecat0, 160, g_ecat0 + 32, 8, i - S0);
    else if (i < S2)  spmmE4(g_cntU, g_ellU, g_valU, g_ecat0, 160, g_ecat0 + 96, 8, i - S1);
}
__global__ void hop0b() {
    cudaGridDependencySynchronize();
    int i = blockIdx.x * blockDim.x + threadIdx.x;
    const int S0 = NN*16, S1 = S0 + NE*8, S2 = S1 + NE*8;
    if (i < S0)       spmmE4(g_cntA, g_ellA, nullptr, g_ncat0 + 64, 192, g_ncat0 + 128, 16, i);
    else if (i < S1)  spmmE4(g_cntL, g_ellL, g_valL, g_ecat0 + 32, 160, g_ecat0 + 64, 8, i - S0);
    else if (i < S2)  spmmE4(g_cntU, g_ellU, g_valU, g_ecat0 + 96, 160, g_ecat0 + 128, 8, i - S1);
}
// hop1: float8 granularity (already occupancy-saturated)
__global__ void hop1a() {
    cudaGridDependencySynchronize();
    int i = blockIdx.x * blockDim.x + threadIdx.x;
    const int S0 = NN*16, S1 = S0 + NE*16, S2 = S1 + NE*16;
    if (i < S0)       spmmE8(g_cntA, g_ellA, nullptr, g_ncat1, 384, g_ncat1 + 128, 16, i);
    else if (i < S1)  spmmE8(g_cntL, g_ellL, g_valL, g_ecat1, 640, g_ecat1 + 128, 16, i - S0);
    else if (i < S2)  spmmE8(g_cntU, g_ellU, g_valU, g_ecat1, 640, g_ecat1 + 384, 16, i - S1);
}
__global__ void hop1b() {
    cudaGridDependencySynchronize();
    int i = blockIdx.x * blockDim.x + threadIdx.x;
    const int S0 = NN*16, S1 = S0 + NE*16, S2 = S1 + NE*16;
    if (i < S0)       spmmE8(g_cntA, g_ellA, nullptr, g_ncat1 + 128, 384, g_ncat1 + 256, 16, i);
    else if (i < S1)  spmmE8(g_cntL, g_ellL, g_valL, g_ecat1 + 128, 640, g_ecat1 + 256, 16, i - S0);
    else if (i < S2)  spmmE8(g_cntU, g_ellU, g_valU, g_ecat1 + 384, 640, g_ecat1 + 512, 16, i - S1);
}

// ---------------- GEMM: BM=64, BN=128, BK=16, 128 threads, 8x8 tile, f32x2 ----------------
struct GD {
    const float* A; const float* B; const float* bias; float* C;
    int K, lda, ldc, biasRows, relu, tiles;
};

__global__ void __launch_bounds__(128)
gemm3(GD d0, GD d1, GD d2) {
    cudaGridDependencySynchronize();
    GD d; int t = blockIdx.x;
    if (t < d0.tiles) d = d0;
    else if (t < d0.tiles + d1.tiles) { d = d1; t -= d0.tiles; }
    else { d = d2; t -= d0.tiles + d1.tiles; }
    int m0 = t * 64;

    __shared__ float As[16][68];
    __shared__ float Bs[16][128];
    int tid = threadIdx.x;
    int tx = tid & 15;   // col group *8 (4 f32x2 pairs)
    int ty = tid >> 4;   // row group *8

    unsigned long long acc[8][4];
#pragma unroll
    for (int i = 0; i < 8; i++)
#pragma unroll
        for (int j = 0; j < 4; j++) acc[i][j] = 0ull;

    for (int k0 = 0; k0 < d.K; k0 += 16) {
#pragma unroll
        for (int i = 0; i < 2; i++) {
            int lin = tid + i * 128;
            int m = lin >> 2;
            int k4 = (lin & 3) * 4;
            float4 f = *(const float4*)(d.A + (size_t)(m0 + m) * d.lda + k0 + k4);
            As[k4 + 0][m] = f.x; As[k4 + 1][m] = f.y;
            As[k4 + 2][m] = f.z; As[k4 + 3][m] = f.w;
        }
#pragma unroll
        for (int i = 0; i < 4; i++) {
            int lin = tid + i * 128;
            int k = lin >> 5, n4 = (lin & 31) * 4;
            *(float4*)&Bs[k][n4] = *(const float4*)(d.B + (size_t)(k0 + k) * 128 + n4);
        }
        __syncthreads();
#pragma unroll
        for (int k = 0; k < 16; k++) {
            float a[8];
            *(float4*)&a[0] = *(const float4*)&As[k][ty * 8];
            *(float4*)&a[4] = *(const float4*)&As[k][ty * 8 + 4];
            ulonglong2 bp0 = *(const ulonglong2*)&Bs[k][tx * 8];
            ulonglong2 bp1 = *(const ulonglong2*)&Bs[k][tx * 8 + 4];
            unsigned long long b[4] = { bp0.x, bp0.y, bp1.x, bp1.y };
#pragma unroll
            for (int i = 0; i < 8; i++) {
                unsigned long long aa = pack_dup(a[i]);
#pragma unroll
                for (int j = 0; j < 4; j++) fma2(acc[i][j], aa, b[j]);
            }
        }
        __syncthreads();
    }

    float bb[8] = {0,0,0,0,0,0,0,0};
    for (int r = 0; r < d.biasRows; r++)
#pragma unroll
        for (int j = 0; j < 8; j++) bb[j] += d.bias[r * 128 + tx * 8 + j];

#pragma unroll
    for (int i = 0; i < 8; i++) {
        int row = m0 + ty * 8 + i;
        float o[8];
#pragma unroll
        for (int j = 0; j < 4; j++) {
            o[2*j]   = lo32(acc[i][j]) + bb[2*j];
            o[2*j+1] = hi32(acc[i][j]) + bb[2*j+1];
        }
        if (d.relu) {
#pragma unroll
            for (int j = 0; j < 8; j++) o[j] = fmaxf(o[j], 0.f);
        }
        *(float4*)(d.C + (size_t)row * d.ldc + tx * 8)     = *(float4*)&o[0];
        *(float4*)(d.C + (size_t)row * d.ldc + tx * 8 + 4) = *(float4*)&o[4];
    }
}

// ---------------- head GEMM (BM=64, BN=64, K=128, f32x2) ----------------
struct GH {
    const float* A; const float* A2; const float* abias;
    const float* B; const float* bias; float* C; int tiles;
};

__global__ void __launch_bounds__(256)
gemmHead(GH d0, GH d1) {
    cudaGridDependencySynchronize();
    GH d; int t = blockIdx.x;
    if (t < d0.tiles) d = d0; else { d = d1; t -= d0.tiles; }
    int m0 = t * 64;

    __shared__ float As[16][72];
    __shared__ float Bs[16][64];
    int tid = threadIdx.x;
    int tx = tid & 15;   // col group *4 (2 pairs)
    int ty = tid >> 4;   // row group *4

    unsigned long long acc[4][2];
#pragma unroll
    for (int i = 0; i < 4; i++) { acc[i][0] = 0ull; acc[i][1] = 0ull; }

    for (int k0 = 0; k0 < 128; k0 += 16) {
        {
            int m = tid >> 2, k4 = (tid & 3) * 4;
            size_t off = (size_t)(m0 + m) * 128 + k0 + k4;
            float4 f = *(const float4*)(d.A + off);
            if (d.A2) {
                float4 g = *(const float4*)(d.A2 + off);
                float4 bz = *(const float4*)(d.abias + k0 + k4);
                f.x = fmaxf(f.x + g.x + bz.x, 0.f);
                f.y = fmaxf(f.y + g.y + bz.y, 0.f);
                f.z = fmaxf(f.z + g.z + bz.z, 0.f);
                f.w = fmaxf(f.w + g.w + bz.w, 0.f);
            }
            As[k4 + 0][m] = f.x; As[k4 + 1][m] = f.y;
            As[k4 + 2][m] = f.z; As[k4 + 3][m] = f.w;
        }
        {
            int k = tid >> 4, n4 = (tid & 15) * 4;
            *(float4*)&Bs[k][n4] = *(const float4*)(d.B + (size_t)(k0 + k) * 64 + n4);
        }
        __syncthreads();
#pragma unroll
        for (int k = 0; k < 16; k++) {
            float a[4];
            *(float4*)&a[0] = *(const float4*)&As[k][ty * 4];
            ulonglong2 bp = *(const ulonglong2*)&Bs[k][tx * 4];
            unsigned long long b0 = bp.x, b1 = bp.y;
#pragma unroll
            for (int i = 0; i < 4; i++) {
                unsigned long long aa = pack_dup(a[i]);
                fma2(acc[i][0], aa, b0);
                fma2(acc[i][1], aa, b1);
            }
        }
        __syncthreads();
    }

    float bb[4];
#pragma unroll
    for (int j = 0; j < 4; j++) bb[j] = d.bias[tx * 4 + j];

#pragma unroll
    for (int i = 0; i < 4; i++) {
        int r = m0 + ty * 4 + i;
        float4 o;
        o.x = lo32(acc[i][0]) + bb[0];
        o.y = hi32(acc[i][0]) + bb[1];
        o.z = lo32(acc[i][1]) + bb[2];
        o.w = hi32(acc[i][1]) + bb[3];
        *(float4*)(d.C + (size_t)r * 64 + tx * 4) = o;
    }
}

// ---------------- host ----------------
static inline int cdiv(int a, int b) { return (a + b - 1) / b; }

template <typename F, typename... Args>
static inline void launch_pdl(F f, int grid, int block, Args... args) {
    cudaLaunchConfig_t cfg = {};
    cfg.gridDim = dim3((unsigned)grid, 1, 1);
    cfg.blockDim = dim3((unsigned)block, 1, 1);
    cfg.stream = 0;
    cudaLaunchAttribute at[1];
    at[0].id = cudaLaunchAttributeProgrammaticStreamSerialization;
    at[0].val.programmaticStreamSerializationAllowed = 1;
    cfg.attrs = at;
    cfg.numAttrs = 1;
    cudaLaunchKernelEx(&cfg, f, args...);
}

extern "C" void kernel_launch(void* const* d_in, const int* in_sizes, int n_in,
                              void* d_out, int out_size) {
    const float* x    = (const float*)d_in[0];
    const float* ex   = (const float*)d_in[1];
    const int*   nei  = (const int*)  d_in[2];
    const int*   eil  = (const int*)  d_in[3];
    const float* eal  = (const float*)d_in[4];
    const int*   eiu  = (const int*)  d_in[5];
    const float* eau  = (const float*)d_in[6];
    const float* nW0  = (const float*)d_in[7];
    const float* nb0  = (const float*)d_in[8];
    const float* nW1  = (const float*)d_in[9];
    const float* nb1  = (const float*)d_in[10];
    const float* fnW  = (const float*)d_in[11];
    const float* fnb  = (const float*)d_in[12];
    const float* eWl0 = (const float*)d_in[13];
    const float* eWu0 = (const float*)d_in[14];
    const float* eb0  = (const float*)d_in[15];
    const float* eWl1 = (const float*)d_in[16];
    const float* eWu1 = (const float*)d_in[17];
    const float* eb1  = (const float*)d_in[18];
    const float* feW  = (const float*)d_in[19];
    const float* feb  = (const float*)d_in[20];
    float* out = (float*)d_out;

    void* p;
    float *ncat0, *ncat1, *hn, *ecat0, *ecat1, *he, *he2, *ws0, *ws1;
    cudaGetSymbolAddress(&p, g_ncat0); ncat0 = (float*)p;
    cudaGetSymbolAddress(&p, g_ncat1); ncat1 = (float*)p;
    cudaGetSymbolAddress(&p, g_hn);    hn    = (float*)p;
    cudaGetSymbolAddress(&p, g_ecat0); ecat0 = (float*)p;
    cudaGetSymbolAddress(&p, g_ecat1); ecat1 = (float*)p;
    cudaGetSymbolAddress(&p, g_he);    he    = (float*)p;
    cudaGetSymbolAddress(&p, g_he2);   he2   = (float*)p;
    cudaGetSymbolAddress(&p, g_ws0);   ws0   = (float*)p;
    cudaGetSymbolAddress(&p, g_ws1);   ws1   = (float*)p;

    GD dz = { nullptr, nullptr, nullptr, nullptr, 0, 0, 0, 0, 0, 0 };
    GH gz = { nullptr, nullptr, nullptr, nullptr, nullptr, nullptr, 0 };

    // 1) init
    launch_pdl(init_k, 256, 256, eWl0, eWu0, eWl1, eWu1, x, ex);
    // 2-3) graph build
    launch_pdl(p1_all, cdiv(NE + 2*NLG, 256), 256, nei, eil, eiu);
    launch_pdl(p2_fill, cdiv(NE + 2*NLG, 256), 256, nei, eil, eiu, eal, eau);
    // 4-5) layer-0 hops (float4 granularity)
    launch_pdl(hop0a, cdiv(NN*16 + NE*16, 256), 256);
    launch_pdl(hop0b, cdiv(NN*16 + NE*16, 256), 256);
    // 6) layer-0 GEMMs: node 64 tiles K=192 + edge 128 tiles K=160
    {
        GD dn = { ncat0, nW0, nb0, ncat1, 192, 192, 384, 3, 1, NN/64 };
        GD de = { ecat0, ws0, eb0, ecat1, 160, 160, 640, 1, 1, NE/64 };
        launch_pdl(gemm3, dn.tiles + de.tiles, 128, dn, de, dz);
    }
    // 7-8) layer-1 hops
    launch_pdl(hop1a, cdiv(NN*16 + NE*32, 256), 256);
    launch_pdl(hop1b, cdiv(NN*16 + NE*32, 256), 256);
    // 9) layer-1 GEMMs: node K=384 + edge split-K 2x320 (raw partials)
    {
        GD dn  = { ncat1, nW1, nb1, hn, 384, 384, 128, 3, 1, NN/64 };
        GD de0 = { ecat1,       ws1,           nullptr, he,  320, 640, 128, 0, 0, NE/64 };
        GD de1 = { ecat1 + 320, ws1 + 320*128, nullptr, he2, 320, 640, 128, 0, 0, NE/64 };
        launch_pdl(gemm3, dn.tiles + de0.tiles + de1.tiles, 128, dn, de0, de1);
    }
    // 10) output heads (edge head fuses relu(he + he2 + eb1))
    {
        GH dn = { hn, nullptr, nullptr, fnW, fnb, out, NN/64 };
        GH de = { he, he2, eb1, feW, feb, out + (size_t)NN * 64, NE/64 };
        launch_pdl(gemmHead, dn.tiles + de.tiles, 256, dn, de);
    }

    (void)in_sizes; (void)n_in; (void)out_size;
}